// round 1
// baseline (speedup 1.0000x reference)
#include <cuda_runtime.h>
#include <cuda_bf16.h>
#include <math.h>

// Soft joint histogram: out[b,k,j] = (1/N) * sum_n phi_k(x[b,n]) * phi_j(y[b,n])
// phi is a difference of sigmoids with width W = L/2.5, L = 1/256.
// phi decays as exp(-2.5*m) per bin offset m -> truncate at radius 4 (9 bins).

#define KBINS     256
#define RAD       4
#define WIN       9            // 2*RAD+1 bins
#define NEDGE     10           // WIN+1 sigmoid edges
#define SLAB_ROWS 128
#define NSLABS    2            // 256 / SLAB_ROWS
#define NCHUNK    9            // pixel chunks -> grid = 8*2*9 = 144 blocks
#define PITCH     260          // smem row pitch in floats (16B-aligned rows)
#define NPIX      65536        // 256*256 pixels per batch
#define BMAX      8
#define CHUNK_PX  7282         // ceil(NPIX/NCHUNK)
#define NTHREADS  512

// Workspace: one 128x256 partial slab per block. 144 * 32768 floats = 18.9 MB.
__device__ float g_ws[BMAX * NSLABS * NCHUNK * SLAB_ROWS * KBINS];

// Compute phi for the 9 bins [k0-4, k0+4] around value v (v in [0,1)).
// Edge argument z_m = (v*256 - m) * 2.5 for edge m = k0-4 .. k0+5.
// E_m = exp(-z_m) = E_0 * exp(2.5)^m. s_m = 1/(1+E_m). phi_i = s_i - s_{i+1}.
// All 10 reciprocals via prefix/suffix products + a single rcp.approx.
__device__ __forceinline__ void compute_phis(float t, int k0, float* __restrict__ phi) {
    const float R = 12.182493960703473f;   // exp(2.5)
    float z0 = (t - (float)(k0 - RAD)) * 2.5f;   // in [10, 12.5)
    float E = __expf(-z0);                       // >= exp(-12.5) ~ 3.7e-6

    float A[NEDGE];
    float Ei = E;
#pragma unroll
    for (int m = 0; m < NEDGE; m++) { A[m] = 1.0f + Ei; Ei *= R; }

    float pre[NEDGE], suf[NEDGE];
    pre[0] = A[0];
#pragma unroll
    for (int m = 1; m < NEDGE; m++) pre[m] = pre[m - 1] * A[m];
    suf[NEDGE - 1] = A[NEDGE - 1];
#pragma unroll
    for (int m = NEDGE - 2; m >= 0; m--) suf[m] = suf[m + 1] * A[m];

    float inv;
    asm("rcp.approx.f32 %0, %1;" : "=f"(inv) : "f"(pre[NEDGE - 1]));

    float s[NEDGE];
    s[0] = suf[1] * inv;
#pragma unroll
    for (int m = 1; m < NEDGE - 1; m++) s[m] = pre[m - 1] * suf[m + 1] * inv;
    s[NEDGE - 1] = pre[NEDGE - 2] * inv;

#pragma unroll
    for (int i = 0; i < WIN; i++) phi[i] = s[i] - s[i + 1];
}

__global__ void __launch_bounds__(NTHREADS, 1)
hist_kernel(const float* __restrict__ x, const float* __restrict__ y) {
    extern __shared__ float sh[];
    const int c    = blockIdx.x;   // pixel chunk
    const int slab = blockIdx.y;   // row slab
    const int b    = blockIdx.z;   // batch
    const int slab_lo = slab * SLAB_ROWS;

    // zero the slab histogram
    for (int i = threadIdx.x; i < SLAB_ROWS * PITCH; i += NTHREADS) sh[i] = 0.0f;
    __syncthreads();

    const int start = c * CHUNK_PX;
    const int end   = min(start + CHUNK_PX, NPIX);
    const float* __restrict__ xb = x + b * NPIX;
    const float* __restrict__ yb = y + b * NPIX;

    for (int p = start + threadIdx.x; p < end; p += NTHREADS) {
        float xv = xb[p];
        float tx = xv * 256.0f;
        int kx = (int)tx;                      // x in [0,1) -> kx in [0,255]
        // window [kx-4, kx+4] must intersect [slab_lo, slab_lo+128)
        if (kx < slab_lo - RAD || kx > slab_lo + SLAB_ROWS - 1 + RAD) continue;

        float yv = yb[p];
        float ty = yv * 256.0f;
        int ky = (int)ty;

        float phi1[WIN], phi2[WIN];
        compute_phis(tx, kx, phi1);
        compute_phis(ty, ky, phi2);

        const int cbase = ky - RAD;
#pragma unroll
        for (int i = 0; i < WIN; i++) {
            int row = kx - RAD + i;
            if (row < slab_lo || row >= slab_lo + SLAB_ROWS) continue;
            float* rp = &sh[(row - slab_lo) * PITCH + cbase];
            float p1 = phi1[i];
#pragma unroll
            for (int j = 0; j < WIN; j++) {
                int col = cbase + j;
                if (col >= 0 && col < KBINS)
                    atomicAdd(&rp[j], p1 * phi2[j]);
            }
        }
    }
    __syncthreads();

    // flush slab to workspace (coalesced STG.128, no atomics)
    float4* __restrict__ dst =
        (float4*)&g_ws[(size_t)(((b * NSLABS) + slab) * NCHUNK + c) * (SLAB_ROWS * KBINS)];
    for (int i = threadIdx.x; i < SLAB_ROWS * KBINS / 4; i += NTHREADS) {
        int row = i >> 6;          // 64 float4 per 256-col row
        int c4  = i & 63;
        const float4* src = (const float4*)&sh[row * PITCH];
        dst[i] = src[c4];
    }
}

__global__ void reduce_kernel(float* __restrict__ out, int total) {
    int idx = blockIdx.x * blockDim.x + threadIdx.x;
    if (idx >= total) return;
    int j = idx & 255;
    int k = (idx >> 8) & 255;
    int b = idx >> 16;
    int slab = k >> 7;             // SLAB_ROWS = 128
    int row  = k & 127;
    const float* __restrict__ base =
        &g_ws[(size_t)((b * NSLABS + slab) * NCHUNK) * (SLAB_ROWS * KBINS) + row * KBINS + j];
    float s = 0.0f;
#pragma unroll
    for (int cc = 0; cc < NCHUNK; cc++) s += base[cc * (SLAB_ROWS * KBINS)];
    out[idx] = s * (1.0f / (float)NPIX);
}

extern "C" void kernel_launch(void* const* d_in, const int* in_sizes, int n_in,
                              void* d_out, int out_size) {
    const float* x = (const float*)d_in[0];
    const float* y = (const float*)d_in[1];
    float* out = (float*)d_out;

    int B = in_sizes[0] / NPIX;    // 8

    size_t smem = (size_t)SLAB_ROWS * PITCH * sizeof(float);  // 130 KB
    cudaFuncSetAttribute(hist_kernel, cudaFuncAttributeMaxDynamicSharedMemorySize, (int)smem);

    dim3 grid(NCHUNK, NSLABS, B);
    hist_kernel<<<grid, NTHREADS, smem>>>(x, y);

    int total = B * KBINS * KBINS;
    reduce_kernel<<<(total + 255) / 256, 256>>>(out, total);
}

// round 4
// speedup vs baseline: 1.4659x; 1.4659x over previous
#include <cuda_runtime.h>
#include <cuda_bf16.h>
#include <math.h>

// Soft joint histogram: out[b,k,j] = (1/N) * sum_n phi_k(x[b,n]) * phi_j(y[b,n])
// phi = difference of sigmoids, width W = L/2.5. Truncate stencil to the
// diamond |di|+|dj| <= 5 inside a 9x9 window (products decay e^{-2.5 per bin}).

#define KBINS     256
#define RAD       4
#define WIN       9
#define NEDGE     10
#define SLAB_ROWS 128
#define NSLABS    2
#define NCHUNK    9            // grid = 8*2*9 = 144 blocks (one wave)
#define PROWS     144          // 128 real rows + 8 pad each side
#define PITCH     264          // padded col pitch (256 + 4 each side, 16B-aligned)
#define NPIX      65536
#define BMAX      8
#define CHUNK_PX  7282
#define NTHREADS  512

// Workspace: one 128x256 partial per block. 144 * 32768 floats = 18.9 MB.
__device__ float g_ws[BMAX * NSLABS * NCHUNK * SLAB_ROWS * KBINS];

// phi for the 9 bins around value t (= x*256), k0 = floor bin.
// One __expf + one rcp.approx via prefix/suffix products of A_m = 1 + E0*R^m.
__device__ __forceinline__ void compute_phis(float t, int k0, float* __restrict__ phi) {
    const float R = 12.182493960703473f;   // exp(2.5)
    float z0 = (t - (float)(k0 - RAD)) * 2.5f;   // in [10, 12.5)
    float E = __expf(-z0);

    float A[NEDGE];
    float Ei = E;
#pragma unroll
    for (int m = 0; m < NEDGE; m++) { A[m] = 1.0f + Ei; Ei *= R; }

    float pre[NEDGE], suf[NEDGE];
    pre[0] = A[0];
#pragma unroll
    for (int m = 1; m < NEDGE; m++) pre[m] = pre[m - 1] * A[m];
    suf[NEDGE - 1] = A[NEDGE - 1];
#pragma unroll
    for (int m = NEDGE - 2; m >= 0; m--) suf[m] = suf[m + 1] * A[m];

    float inv;
    asm("rcp.approx.f32 %0, %1;" : "=f"(inv) : "f"(pre[NEDGE - 1]));

    float s[NEDGE];
    s[0] = suf[1] * inv;
#pragma unroll
    for (int m = 1; m < NEDGE - 1; m++) s[m] = pre[m - 1] * suf[m + 1] * inv;
    s[NEDGE - 1] = pre[NEDGE - 2] * inv;

#pragma unroll
    for (int i = 0; i < WIN; i++) phi[i] = s[i] - s[i + 1];
}

// diamond half-widths per row offset ii=0..8: jj in [4-w, 4+w]
__device__ __constant__ int kJLo[WIN] = {3, 2, 1, 0, 0, 0, 1, 2, 3};
__device__ __constant__ int kJHi[WIN] = {5, 6, 7, 8, 8, 8, 7, 6, 5};

__global__ void __launch_bounds__(NTHREADS, 1)
hist_kernel(const float* __restrict__ x, const float* __restrict__ y) {
    extern __shared__ float sh[];
    const int c    = blockIdx.x;
    const int slab = blockIdx.y;
    const int b    = blockIdx.z;
    const int slab_lo = slab * SLAB_ROWS;

    for (int i = threadIdx.x; i < PROWS * PITCH; i += NTHREADS) sh[i] = 0.0f;
    __syncthreads();

    const int start = c * CHUNK_PX;
    const int end   = min(start + CHUNK_PX, NPIX);
    const float* __restrict__ xb = x + b * NPIX;
    const float* __restrict__ yb = y + b * NPIX;

    for (int p = start + threadIdx.x; p < end; p += NTHREADS) {
        float tx = xb[p] * 256.0f;
        int kx = (int)tx;
        if (kx < slab_lo - RAD || kx > slab_lo + SLAB_ROWS - 1 + RAD) continue;

        float ty = yb[p] * 256.0f;
        int ky = (int)ty;

        float phi1[WIN], phi2[WIN];
        compute_phis(tx, kx, phi1);
        compute_phis(ty, ky, phi2);

        // padded coords: row_mem = (kx - slab_lo + 4) + ii in [0,143]
        //                col_mem = ky + jj            in [0,263]
        float* base = &sh[(kx - slab_lo + 4) * PITCH + ky];
#pragma unroll
        for (int ii = 0; ii < WIN; ii++) {
            float* rp = base + ii * PITCH;
            float p1 = phi1[ii];
            const int jlo = (ii < 4) ? (4 - (4 - ii) + ((ii < 4) ? (3 - ii >= 0 ? 0 : 0) : 0)) : 0; // placeholder
            (void)jlo;
#pragma unroll
            for (int jj = 0; jj < WIN; jj++) {
                // diamond: |ii-4| + |jj-4| <= 5 (compile-time predicate)
                const int di = (ii < 4) ? (4 - ii) : (ii - 4);
                const int dj = (jj < 4) ? (4 - jj) : (jj - 4);
                if (di + dj <= 5)
                    atomicAdd(&rp[jj], p1 * phi2[jj]);
            }
        }
    }
    __syncthreads();

    // flush real 128x256 region (rows 8..135, cols 4..259) -> workspace
    float4* __restrict__ dst =
        (float4*)&g_ws[(size_t)(((b * NSLABS) + slab) * NCHUNK + c) * (SLAB_ROWS * KBINS)];
    for (int i = threadIdx.x; i < SLAB_ROWS * KBINS / 4; i += NTHREADS) {
        int row = i >> 6;          // 64 float4 per 256-col row
        int c4  = i & 63;
        const float4* src = (const float4*)&sh[(row + 8) * PITCH + 4];
        dst[i] = src[c4];
    }
}

__global__ void reduce_kernel(float* __restrict__ out, int total4) {
    int idx = blockIdx.x * blockDim.x + threadIdx.x;   // float4 index
    if (idx >= total4) return;
    // idx indexes (b, k, j4): j4 = idx % 64, k = (idx/64) % 256, b = idx/16384
    int k = (idx >> 6) & 255;
    int b = idx >> 14;
    int slab = k >> 7;
    int rowj4 = ((k & 127) << 6) | (idx & 63);   // (row*256 + j)/4 within slab
    const float4* __restrict__ base = (const float4*)
        &g_ws[(size_t)((b * NSLABS + slab) * NCHUNK) * (SLAB_ROWS * KBINS)];
    float4 s = make_float4(0.f, 0.f, 0.f, 0.f);
#pragma unroll
    for (int cc = 0; cc < NCHUNK; cc++) {
        float4 v = base[(size_t)cc * (SLAB_ROWS * KBINS / 4) + rowj4];
        s.x += v.x; s.y += v.y; s.z += v.z; s.w += v.w;
    }
    const float inv = 1.0f / (float)NPIX;
    s.x *= inv; s.y *= inv; s.z *= inv; s.w *= inv;
    ((float4*)out)[idx] = s;
}

extern "C" void kernel_launch(void* const* d_in, const int* in_sizes, int n_in,
                              void* d_out, int out_size) {
    const float* x = (const float*)d_in[0];
    const float* y = (const float*)d_in[1];
    float* out = (float*)d_out;

    int B = in_sizes[0] / NPIX;

    size_t smem = (size_t)PROWS * PITCH * sizeof(float);  // 152 KB
    cudaFuncSetAttribute(hist_kernel, cudaFuncAttributeMaxDynamicSharedMemorySize, (int)smem);

    dim3 grid(NCHUNK, NSLABS, B);
    hist_kernel<<<grid, NTHREADS, smem>>>(x, y);

    int total4 = B * KBINS * KBINS / 4;
    reduce_kernel<<<(total4 + 255) / 256, 256>>>(out, total4);
}